// round 5
// baseline (speedup 1.0000x reference)
#include <cuda_runtime.h>
#include <cuda_bf16.h>
#include <cstdint>

#define BQ   2048
#define DD   128
#define MM   256
#define NK   32768
#define EST_CONST 0.0048957583f   // sqrt(pi/2)/256

#define TILE_N 64
#define NCB    (NK / TILE_N)      // 512 column blocks

// ---------------- device scratch ----------------
__device__ __align__(16) signed char g_A1[BQ * MM];   // hi digit of projected query
__device__ __align__(16) signed char g_A2[BQ * MM];   // lo digit
__device__ __align__(16) signed char g_B[NK * MM];    // keys int8 (+/-1)
__device__ float g_qscl[BQ];                          // per-row quant scale q
__device__ float g_scl[NK];                           // EST_CONST * key_norms
__device__ float g_pmax[BQ * NCB];                    // [row][cb]
__device__ float g_psum[BQ * NCB];
__device__ float g_rowm[BQ];
__device__ float g_rowinv[BQ];

__device__ __forceinline__ uint32_t smem_u32(const void* p) {
    uint32_t a;
    asm("{ .reg .u64 t; cvta.to.shared.u64 t, %1; cvt.u32.u64 %0, t; }" : "=r"(a) : "l"(p));
    return a;
}
#define CP16(dst, src) asm volatile("cp.async.cg.shared.global [%0], [%1], 16;" :: "r"(dst), "l"(src))
#define CP_COMMIT()    asm volatile("cp.async.commit_group;" ::: "memory")

// ---------------- kernel 0: convert keys (float +/-1 -> int8) + scales ------
__global__ __launch_bounds__(256) void convert_keys_kernel(const float* __restrict__ keys,
                                                           const float* __restrict__ norms) {
    int i = blockIdx.x * blockDim.x + threadIdx.x;    // over float4, NK*MM/4
    float4 v = ((const float4*)keys)[i];
    char4 c;
    c.x = (signed char)v.x; c.y = (signed char)v.y;
    c.z = (signed char)v.z; c.w = (signed char)v.w;
    ((char4*)g_B)[i] = c;
    if (i < NK) g_scl[i] = EST_CONST * norms[i];
}

// ---------------- kernel 1: project query + dual int8 quantize --------------
__global__ __launch_bounds__(256) void proj_kernel(const float* __restrict__ q,
                                                   const float* __restrict__ S) {
    __shared__ float qs[16][128];
    __shared__ float pqS[16][260];
    __shared__ float rowS[16];          // 32512 / rowmax
    int blk = blockIdx.x, tid = threadIdx.x;
    int wid = tid >> 5, lane = tid & 31;
#pragma unroll
    for (int p = 0; p < 8; p++) {
        int e = p * 256 + tid;
        qs[e >> 7][e & 127] = q[blk * 16 * DD + e];
    }
    __syncthreads();
    int m = tid;
    float acc[16];
#pragma unroll
    for (int i = 0; i < 16; i++) acc[i] = 0.f;
    for (int d = 0; d < DD; d++) {
        float sv = S[m * DD + d];
#pragma unroll
        for (int i = 0; i < 16; i++) acc[i] += qs[i][d] * sv;
    }
#pragma unroll
    for (int i = 0; i < 16; i++) pqS[i][m] = acc[i];
    __syncthreads();
    // row max reduction: warp w handles rows 2w, 2w+1
#pragma unroll
    for (int j = 0; j < 2; j++) {
        int r = wid * 2 + j;
        float mx = 0.f;
#pragma unroll
        for (int c = 0; c < 8; c++) mx = fmaxf(mx, fabsf(pqS[r][lane + c * 32]));
#pragma unroll
        for (int o = 16; o; o >>= 1) mx = fmaxf(mx, __shfl_xor_sync(0xffffffff, mx, o));
        if (lane == 0) {
            float mxx = fmaxf(mx, 1e-20f);
            rowS[r] = 32512.f / mxx;
            g_qscl[blk * 16 + r] = mxx / 32512.f;
        }
    }
    __syncthreads();
#pragma unroll
    for (int i = 0; i < 16; i++) {
        int b = blk * 16 + i;
        float x = pqS[i][m] * rowS[i];
        float hi = rintf(x * (1.0f / 256.0f));
        hi = fminf(fmaxf(hi, -127.f), 127.f);
        float lo = rintf(x - 256.f * hi);
        lo = fminf(fmaxf(lo, -128.f), 127.f);
        g_A1[b * MM + m] = (signed char)(int)hi;
        g_A2[b * MM + m] = (signed char)(int)lo;
    }
}

// ---------------- kernel 2: dual-digit int8 GEMM + softmax partials ----------
// CTA 128 rows x 64 keys; K=256 bytes in 4 chunks of 64; 3-stage cp.async.
// smem stage: A1 128x80 | A2 128x80 | B 64x80 = 25600 B; 3 stages = 76800 B.
#define RS 80
#define A1SZ (128 * RS)              // 10240
#define BOFF (2 * A1SZ)              // 20480
#define STAGE_BYTES (BOFF + 64 * RS) // 25600
#define SMEM_BYTES  (3 * STAGE_BYTES)

extern __shared__ char dsm[];

__device__ __forceinline__ void load_chunk(uint32_t sb, int stage, int kc,
                                           int row0, int col0, int tid) {
    uint32_t base = sb + stage * STAGE_BYTES;
#pragma unroll
    for (int i = 0; i < 2; i++) {
        int u = tid + i * 256;
        int r = u >> 2, c = u & 3;
        uint32_t off = (uint32_t)(r * RS + c * 16);
        CP16(base + off,        &g_A1[(size_t)(row0 + r) * MM + kc + c * 16]);
        CP16(base + A1SZ + off, &g_A2[(size_t)(row0 + r) * MM + kc + c * 16]);
    }
    {
        int r = tid >> 2, c = tid & 3;
        CP16(base + BOFF + (uint32_t)(r * RS + c * 16),
             &g_B[(size_t)(col0 + r) * MM + kc + c * 16]);
    }
}

#define IMMA(acc, a, b0, b1) \
    asm volatile("mma.sync.aligned.m16n8k32.row.col.s32.s8.s8.s32 " \
                 "{%0,%1,%2,%3}, {%4,%5,%6,%7}, {%8,%9}, {%0,%1,%2,%3};" \
                 : "+r"((acc)[0]), "+r"((acc)[1]), "+r"((acc)[2]), "+r"((acc)[3]) \
                 : "r"((a)[0]), "r"((a)[1]), "r"((a)[2]), "r"((a)[3]), \
                   "r"(b0), "r"(b1))

__global__ __launch_bounds__(256, 2) void gemm_kernel(float* __restrict__ out) {
    uint32_t sb = smem_u32(dsm);
    int tid  = threadIdx.x;
    int warp = tid >> 5, lane = tid & 31;
    int wm = warp >> 1, wn = warp & 1;       // 4x2 warps; warp tile 32x32
    int rb = blockIdx.y, cb = blockIdx.x;
    int row0 = rb * 128, col0 = cb * TILE_N;

    __shared__ float sclS[TILE_N];
    __shared__ float qsclS[128];
    __shared__ float redm[128][2];
    __shared__ float reds[128][2];

    if (tid < TILE_N) sclS[tid] = g_scl[col0 + tid];
    if (tid < 128) qsclS[tid] = g_qscl[row0 + tid];

    int acc1[2][4][4], acc2[2][4][4];
#pragma unroll
    for (int i = 0; i < 2; i++)
#pragma unroll
        for (int j = 0; j < 4; j++)
#pragma unroll
            for (int k = 0; k < 4; k++) { acc1[i][j][k] = 0; acc2[i][j][k] = 0; }

    int l15 = lane & 15, h16 = lane >> 4;

    load_chunk(sb, 0, 0, row0, col0, tid); CP_COMMIT();
    load_chunk(sb, 1, 64, row0, col0, tid); CP_COMMIT();

#pragma unroll 1
    for (int c = 0; c < 4; c++) {
        if (c + 2 < 4) {
            load_chunk(sb, (c + 2) % 3, (c + 2) * 64, row0, col0, tid);
            CP_COMMIT();
            asm volatile("cp.async.wait_group 2;" ::: "memory");
        } else {
            asm volatile("cp.async.wait_group 0;" ::: "memory");
        }
        __syncthreads();
        uint32_t base = sb + (c % 3) * STAGE_BYTES;
#pragma unroll
        for (int j = 0; j < 2; j++) {
            uint32_t a1[2][4], a2[2][4];
#pragma unroll
            for (int mf = 0; mf < 2; mf++) {
                uint32_t addr = base + (uint32_t)((wm * 32 + mf * 16 + l15) * RS
                                                  + h16 * 16 + j * 32);
                asm volatile("ldmatrix.sync.aligned.m8n8.x4.shared.b16 {%0,%1,%2,%3}, [%4];"
                             : "=r"(a1[mf][0]), "=r"(a1[mf][1]), "=r"(a1[mf][2]), "=r"(a1[mf][3])
                             : "r"(addr));
                asm volatile("ldmatrix.sync.aligned.m8n8.x4.shared.b16 {%0,%1,%2,%3}, [%4];"
                             : "=r"(a2[mf][0]), "=r"(a2[mf][1]), "=r"(a2[mf][2]), "=r"(a2[mf][3])
                             : "r"(addr + A1SZ));
            }
            uint32_t b[4][2];
#pragma unroll
            for (int nq = 0; nq < 2; nq++) {
                uint32_t r0, r1, r2, r3;
                uint32_t addr = base + BOFF + (uint32_t)((wn * 32 + nq * 16 + l15) * RS
                                                         + h16 * 16 + j * 32);
                asm volatile("ldmatrix.sync.aligned.m8n8.x4.shared.b16 {%0,%1,%2,%3}, [%4];"
                             : "=r"(r0), "=r"(r1), "=r"(r2), "=r"(r3)
                             : "r"(addr));
                b[nq * 2][0] = r0;     b[nq * 2][1] = r2;
                b[nq * 2 + 1][0] = r1; b[nq * 2 + 1][1] = r3;
            }
#pragma unroll
            for (int mf = 0; mf < 2; mf++)
#pragma unroll
                for (int nf = 0; nf < 4; nf++) {
                    IMMA(acc1[mf][nf], a1[mf], b[nf][0], b[nf][1]);
                    IMMA(acc2[mf][nf], a2[mf], b[nf][0], b[nf][1]);
                }
        }
        __syncthreads();
    }

    // ---------------- epilogue ----------------
    float* stage = (float*)dsm;            // [128][68] fp32, aliases cp buffers
    int q  = lane & 3;
    int rq = lane >> 2;

    float rmax[2][2];
#pragma unroll
    for (int mf = 0; mf < 2; mf++)
#pragma unroll
        for (int h = 0; h < 2; h++) rmax[mf][h] = -1e30f;

#pragma unroll
    for (int mf = 0; mf < 2; mf++)
#pragma unroll
        for (int nf = 0; nf < 4; nf++) {
            int col = wn * 32 + nf * 8 + q * 2;
            float s0 = sclS[col], s1 = sclS[col + 1];
#pragma unroll
            for (int h = 0; h < 2; h++) {
                int r = wm * 32 + mf * 16 + h * 8 + rq;
                float qsc = qsclS[r];
                float v0 = (float)(acc1[mf][nf][h * 2 + 0] * 256 + acc2[mf][nf][h * 2 + 0]) * qsc * s0;
                float v1 = (float)(acc1[mf][nf][h * 2 + 1] * 256 + acc2[mf][nf][h * 2 + 1]) * qsc * s1;
                rmax[mf][h] = fmaxf(rmax[mf][h], fmaxf(v0, v1));
                stage[r * 68 + col]     = v0;
                stage[r * 68 + col + 1] = v1;
            }
        }

#pragma unroll
    for (int mf = 0; mf < 2; mf++)
#pragma unroll
        for (int h = 0; h < 2; h++) {
            float m = rmax[mf][h];
            m = fmaxf(m, __shfl_xor_sync(0xffffffff, m, 1));
            m = fmaxf(m, __shfl_xor_sync(0xffffffff, m, 2));
            if (q == 0) redm[wm * 32 + mf * 16 + h * 8 + rq][wn] = m;
        }
    __syncthreads();

#pragma unroll
    for (int mf = 0; mf < 2; mf++)
#pragma unroll
        for (int h = 0; h < 2; h++) {
            int r = wm * 32 + mf * 16 + h * 8 + rq;
            float m = fmaxf(redm[r][0], redm[r][1]);
            float qsc = qsclS[r];
            float s = 0.f;
#pragma unroll
            for (int nf = 0; nf < 4; nf++) {
                int col = wn * 32 + nf * 8 + q * 2;
                float v0 = (float)(acc1[mf][nf][h * 2 + 0] * 256 + acc2[mf][nf][h * 2 + 0]) * qsc * sclS[col];
                float v1 = (float)(acc1[mf][nf][h * 2 + 1] * 256 + acc2[mf][nf][h * 2 + 1]) * qsc * sclS[col + 1];
                s += __expf(v0 - m) + __expf(v1 - m);
            }
            s += __shfl_xor_sync(0xffffffff, s, 1);
            s += __shfl_xor_sync(0xffffffff, s, 2);
            if (q == 0) reds[r][wn] = s;
        }
    __syncthreads();

    if (tid < 128) {
        float m = fmaxf(redm[tid][0], redm[tid][1]);
        float s = reds[tid][0] + reds[tid][1];
        g_pmax[(size_t)(row0 + tid) * NCB + cb] = m;
        g_psum[(size_t)(row0 + tid) * NCB + cb] = s;
    }

    // coalesced tile store: 2 threads per row, 128 B each
    {
        int r2 = tid >> 1, hh = tid & 1;
        const float4* src = (const float4*)&stage[r2 * 68 + hh * 32];
        float4* dst = (float4*)&out[(size_t)(row0 + r2) * NK + col0 + hh * 32];
#pragma unroll
        for (int v4 = 0; v4 < 8; v4++) dst[v4] = src[v4];
    }
}

// ---------------- kernel 3: merge partials (one block per row) ---------------
__global__ __launch_bounds__(256) void reduce_kernel() {
    int b = blockIdx.x, t = threadIdx.x;
    int wid = t >> 5, lane = t & 31;
    __shared__ float sm[8], ss[8];
    float pm0 = g_pmax[(size_t)b * NCB + t];
    float pm1 = g_pmax[(size_t)b * NCB + 256 + t];
    float ps0 = g_psum[(size_t)b * NCB + t];
    float ps1 = g_psum[(size_t)b * NCB + 256 + t];
    float M = fmaxf(pm0, pm1);
#pragma unroll
    for (int o = 16; o; o >>= 1) M = fmaxf(M, __shfl_xor_sync(0xffffffff, M, o));
    if (lane == 0) sm[wid] = M;
    __syncthreads();
    float M0 = sm[lane & 7];
#pragma unroll
    for (int o = 4; o; o >>= 1) M0 = fmaxf(M0, __shfl_xor_sync(0xffffffff, M0, o));
    M = __shfl_sync(0xffffffff, M0, 0);
    float s = ps0 * __expf(pm0 - M) + ps1 * __expf(pm1 - M);
#pragma unroll
    for (int o = 16; o; o >>= 1) s += __shfl_xor_sync(0xffffffff, s, o);
    if (lane == 0) ss[wid] = s;
    __syncthreads();
    if (t == 0) {
        float S = ss[0] + ss[1] + ss[2] + ss[3] + ss[4] + ss[5] + ss[6] + ss[7];
        g_rowm[b] = M;
        g_rowinv[b] = 1.f / S;
    }
}

// ---------------- kernel 4: finalize out = exp(x-m)*inv ----------------------
__global__ __launch_bounds__(256) void finalize_kernel(float* __restrict__ out) {
    size_t i = (size_t)blockIdx.x * blockDim.x + threadIdx.x;
    float4* o4 = (float4*)out;
    int b = (int)(i >> 13);                 // 8192 float4 per row
    float m = g_rowm[b], inv = g_rowinv[b];
    float4 v = o4[i];
    v.x = __expf(v.x - m) * inv;
    v.y = __expf(v.y - m) * inv;
    v.z = __expf(v.z - m) * inv;
    v.w = __expf(v.w - m) * inv;
    o4[i] = v;
}

// ---------------- launcher ---------------------------------------------------
extern "C" void kernel_launch(void* const* d_in, const int* in_sizes, int n_in,
                              void* d_out, int out_size) {
    const float* query  = (const float*)d_in[0];
    const float* keys   = (const float*)d_in[1];
    const float* norms  = (const float*)d_in[2];
    const float* sketch = (const float*)d_in[3];
    float* out = (float*)d_out;

    cudaFuncSetAttribute(gemm_kernel, cudaFuncAttributeMaxDynamicSharedMemorySize, SMEM_BYTES);

    convert_keys_kernel<<<NK * MM / 1024, 256>>>(keys, norms);
    proj_kernel<<<BQ / 16, 256>>>(query, sketch);
    dim3 ggrid(NCB, BQ / 128);
    gemm_kernel<<<ggrid, 256, SMEM_BYTES>>>(out);
    reduce_kernel<<<BQ, 256>>>();
    finalize_kernel<<<(size_t)BQ * NK / 4 / 256, 256>>>(out);
}

// round 6
// speedup vs baseline: 2.0241x; 2.0241x over previous
#include <cuda_runtime.h>
#include <cuda_bf16.h>
#include <cstdint>

#define BQ   2048
#define DD   128
#define MM   256
#define NK   32768
#define EST_CONST 0.0048957583f   // sqrt(pi/2)/256

#define TILE_N 128
#define NCB    (NK / TILE_N)      // 256 column blocks
#define KMAIN  384                // [Qhi|Qlo|Qhi] x [KDhi|KDhi|KDlo]

// ---------------- device scratch ----------------
__device__ __align__(16) __nv_bfloat16 g_Kb[NK * MM];      // keys bf16 exact (16.8 MB)
__device__ __align__(16) __nv_bfloat16 g_Sd[DD * 512];     // S^T hi|lo  [d][512]
__device__ __align__(16) __nv_bfloat16 g_Ap[BQ * KMAIN];   // [Qhi|Qlo|Qhi]
__device__ __align__(16) __nv_bfloat16 g_Bp[NK * KMAIN];   // [KDhi|KDhi|KDlo] (25 MB)
__device__ float g_scl[NK];
__device__ float g_pmax[BQ * NCB];
__device__ float g_psum[BQ * NCB];
__device__ float g_rowm[BQ];
__device__ float g_rowinv[BQ];

__device__ __forceinline__ uint32_t smem_u32(const void* p) {
    uint32_t a;
    asm("{ .reg .u64 t; cvta.to.shared.u64 t, %1; cvt.u32.u64 %0, t; }" : "=r"(a) : "l"(p));
    return a;
}
#define CP16(dst, src) asm volatile("cp.async.cg.shared.global [%0], [%1], 16;" :: "r"(dst), "l"(src))
#define CP_COMMIT()    asm volatile("cp.async.commit_group;" ::: "memory")

// ---------------- kernel 0: keys -> bf16 (exact), scales --------------------
__global__ __launch_bounds__(256) void convert_keys_kernel(const float* __restrict__ keys,
                                                           const float* __restrict__ norms) {
    int i = blockIdx.x * blockDim.x + threadIdx.x;   // over float4
    float4 v = ((const float4*)keys)[i];
    __nv_bfloat162* o = (__nv_bfloat162*)g_Kb;
    o[i * 2]     = __nv_bfloat162(__float2bfloat16(v.x), __float2bfloat16(v.y));
    o[i * 2 + 1] = __nv_bfloat162(__float2bfloat16(v.z), __float2bfloat16(v.w));
    if (i < NK) g_scl[i] = EST_CONST * norms[i];
}

// ---------------- kernel 0b: S -> transposed hi/lo --------------------------
__global__ __launch_bounds__(256) void prep_S_kernel(const float* __restrict__ S) {
    int idx = blockIdx.x * blockDim.x + threadIdx.x;   // 32768 elems
    int m = idx >> 7, d = idx & 127;
    float v = S[m * DD + d];
    __nv_bfloat16 hi = __float2bfloat16(v);
    float lo = v - __bfloat162float(hi);
    g_Sd[d * 512 + m]       = hi;
    g_Sd[d * 512 + 256 + m] = __float2bfloat16(lo);
}

// ---------------- kernel 0c: Q -> [Qhi|Qlo|Qhi] -----------------------------
__global__ __launch_bounds__(256) void prep_A_kernel(const float* __restrict__ q) {
    int idx = blockIdx.x * blockDim.x + threadIdx.x;   // 2048*128
    int b = idx >> 7, d = idx & 127;
    float v = q[idx];
    __nv_bfloat16 hi = __float2bfloat16(v);
    float lo = v - __bfloat162float(hi);
    g_Ap[b * KMAIN + d]       = hi;
    g_Ap[b * KMAIN + 128 + d] = __float2bfloat16(lo);
    g_Ap[b * KMAIN + 256 + d] = hi;
}

// ---------------- shared GEMM machinery ----------------
#define RSE 72                          // smem row elems (144 B)
#define TBYTES (128 * RSE * 2)          // 18432 per operand tile
#define STAGE_BYTES (2 * TBYTES)        // 36864
#define SMEM_BYTES  (3 * STAGE_BYTES)   // 110592

extern __shared__ char dsm[];

#define HMMA(acc, a, b0, b1) \
    asm volatile("mma.sync.aligned.m16n8k16.row.col.f32.bf16.bf16.f32 " \
                 "{%0,%1,%2,%3}, {%4,%5,%6,%7}, {%8,%9}, {%0,%1,%2,%3};" \
                 : "+f"((acc)[0]), "+f"((acc)[1]), "+f"((acc)[2]), "+f"((acc)[3]) \
                 : "r"((a)[0]), "r"((a)[1]), "r"((a)[2]), "r"((a)[3]), "r"(b0), "r"(b1))

// compute one 64-wide K chunk from stage buffer (warp tile 32x64, 4x2 warps)
__device__ __forceinline__ void compute_chunk(uint32_t base, int wm, int wn,
                                              int lrow, int lcolo, float acc[2][8][4]) {
    uint32_t bbase = base + TBYTES;
#pragma unroll
    for (int kk = 0; kk < 64; kk += 16) {
        uint32_t a[2][4];
#pragma unroll
        for (int mf = 0; mf < 2; mf++) {
            uint32_t addr = base + (uint32_t)((wm * 32 + mf * 16 + lrow) * (RSE * 2)
                                              + (kk + lcolo) * 2);
            asm volatile("ldmatrix.sync.aligned.m8n8.x4.shared.b16 {%0,%1,%2,%3}, [%4];"
                         : "=r"(a[mf][0]), "=r"(a[mf][1]), "=r"(a[mf][2]), "=r"(a[mf][3])
                         : "r"(addr));
        }
        uint32_t b[8][2];
#pragma unroll
        for (int nq = 0; nq < 4; nq++) {
            uint32_t r0, r1, r2, r3;
            uint32_t addr = bbase + (uint32_t)((wn * 64 + nq * 16 + lrow) * (RSE * 2)
                                               + (kk + lcolo) * 2);
            asm volatile("ldmatrix.sync.aligned.m8n8.x4.shared.b16 {%0,%1,%2,%3}, [%4];"
                         : "=r"(r0), "=r"(r1), "=r"(r2), "=r"(r3)
                         : "r"(addr));
            b[nq * 2][0] = r0;     b[nq * 2][1] = r2;
            b[nq * 2 + 1][0] = r1; b[nq * 2 + 1][1] = r3;
        }
#pragma unroll
        for (int mf = 0; mf < 2; mf++)
#pragma unroll
            for (int nf = 0; nf < 8; nf++)
                HMMA(acc[mf][nf], a[mf], b[nf][0], b[nf][1]);
    }
}

__device__ __forceinline__ void load_tiles(uint32_t base, int tid,
                                           const __nv_bfloat16* __restrict__ Ag, int astr,
                                           const __nv_bfloat16* __restrict__ Bg, int bstr) {
#pragma unroll
    for (int i = 0; i < 4; i++) {
        int u = tid + i * 256;
        int r = u >> 3, c = (u & 7) * 8;
        uint32_t off = (uint32_t)(r * (RSE * 2) + c * 2);
        CP16(base + off,          &Ag[(size_t)r * astr + c]);
        CP16(base + TBYTES + off, &Bg[(size_t)r * bstr + c]);
    }
}

// ---------------- kernel 1: KD = keys * S (hi/lo), split & pack B' ----------
// CTA: 128 keys x 128 dims, K=512 ([keys|keys] x [Shi|Slo]), 8 chunks.
__global__ __launch_bounds__(256, 2) void kd_kernel() {
    uint32_t sb = smem_u32(dsm);
    int tid = threadIdx.x, warp = tid >> 5, lane = tid & 31;
    int wm = warp >> 1, wn = warp & 1;
    int n0 = blockIdx.x * 128;

    float acc[2][8][4];
#pragma unroll
    for (int i = 0; i < 2; i++)
#pragma unroll
        for (int j = 0; j < 8; j++)
#pragma unroll
            for (int k = 0; k < 4; k++) acc[i][j][k] = 0.f;

    int lrow  = (lane & 7) + (lane & 8);
    int lcolo = (lane >> 4) << 3;

#define KD_LOAD(st, c) load_tiles(sb + (st) * STAGE_BYTES, tid, \
        &g_Kb[(size_t)n0 * MM + (((c) * 64) & 255)], MM, &g_Sd[(c) * 64], 512)

    KD_LOAD(0, 0); CP_COMMIT();
    KD_LOAD(1, 1); CP_COMMIT();
#pragma unroll 1
    for (int c = 0; c < 8; c++) {
        if (c < 7) asm volatile("cp.async.wait_group 1;" ::: "memory");
        else       asm volatile("cp.async.wait_group 0;" ::: "memory");
        __syncthreads();
        if (c + 2 < 8) { KD_LOAD((c + 2) % 3, c + 2); CP_COMMIT(); }
        compute_chunk(sb + (c % 3) * STAGE_BYTES, wm, wn, lrow, lcolo, acc);
    }

    // epilogue: hi/lo split, pack [KDhi|KDhi|KDlo]
    int q = lane & 3, rq = lane >> 2;
#pragma unroll
    for (int mf = 0; mf < 2; mf++)
#pragma unroll
        for (int nf = 0; nf < 8; nf++) {
            int col = wn * 64 + nf * 8 + q * 2;
#pragma unroll
            for (int h = 0; h < 2; h++) {
                int r = wm * 32 + mf * 16 + h * 8 + rq;
                float v0 = acc[mf][nf][h * 2 + 0];
                float v1 = acc[mf][nf][h * 2 + 1];
                __nv_bfloat16 h0 = __float2bfloat16(v0);
                __nv_bfloat16 h1 = __float2bfloat16(v1);
                __nv_bfloat162 hp(h0, h1);
                __nv_bfloat162 lp(__float2bfloat16(v0 - __bfloat162float(h0)),
                                  __float2bfloat16(v1 - __bfloat162float(h1)));
                size_t rb = (size_t)(n0 + r) * KMAIN;
                *(__nv_bfloat162*)&g_Bp[rb + col]       = hp;
                *(__nv_bfloat162*)&g_Bp[rb + 128 + col] = hp;
                *(__nv_bfloat162*)&g_Bp[rb + 256 + col] = lp;
            }
        }
}

// ---------------- kernel 2: main GEMM 2048x32768, K=384 + softmax partials --
__global__ __launch_bounds__(256, 2) void gemm_kernel(float* __restrict__ out) {
    uint32_t sb = smem_u32(dsm);
    int tid = threadIdx.x, warp = tid >> 5, lane = tid & 31;
    int wm = warp >> 1, wn = warp & 1;
    int rb = blockIdx.y, cb = blockIdx.x;
    int row0 = rb * 128, col0 = cb * TILE_N;

    __shared__ float sclS[TILE_N];
    __shared__ float redm[128][2];
    __shared__ float reds[128][2];
    if (tid < TILE_N) sclS[tid] = g_scl[col0 + tid];

    float acc[2][8][4];
#pragma unroll
    for (int i = 0; i < 2; i++)
#pragma unroll
        for (int j = 0; j < 8; j++)
#pragma unroll
            for (int k = 0; k < 4; k++) acc[i][j][k] = 0.f;

    int lrow  = (lane & 7) + (lane & 8);
    int lcolo = (lane >> 4) << 3;

#define MG_LOAD(st, c) load_tiles(sb + (st) * STAGE_BYTES, tid, \
        &g_Ap[(size_t)row0 * KMAIN + (c) * 64], KMAIN, \
        &g_Bp[(size_t)col0 * KMAIN + (c) * 64], KMAIN)

    MG_LOAD(0, 0); CP_COMMIT();
    MG_LOAD(1, 1); CP_COMMIT();
#pragma unroll 1
    for (int c = 0; c < 6; c++) {
        if (c < 5) asm volatile("cp.async.wait_group 1;" ::: "memory");
        else       asm volatile("cp.async.wait_group 0;" ::: "memory");
        __syncthreads();
        if (c + 2 < 6) { MG_LOAD((c + 2) % 3, c + 2); CP_COMMIT(); }
        compute_chunk(sb + (c % 3) * STAGE_BYTES, wm, wn, lrow, lcolo, acc);
    }
    __syncthreads();     // all compute done before epilogue aliases buffers

    // ---------------- epilogue (R4-proven) ----------------
    float* stage = (float*)dsm;            // [128][132] fp32
    int q = lane & 3, rq = lane >> 2;

    float rmax[2][2];
#pragma unroll
    for (int mf = 0; mf < 2; mf++)
#pragma unroll
        for (int h = 0; h < 2; h++) rmax[mf][h] = -1e30f;

#pragma unroll
    for (int mf = 0; mf < 2; mf++)
#pragma unroll
        for (int nf = 0; nf < 8; nf++) {
            int c = wn * 64 + nf * 8 + q * 2;
            float s0 = sclS[c], s1 = sclS[c + 1];
#pragma unroll
            for (int h = 0; h < 2; h++) {
                float v0 = acc[mf][nf][h * 2 + 0] * s0;
                float v1 = acc[mf][nf][h * 2 + 1] * s1;
                acc[mf][nf][h * 2 + 0] = v0;
                acc[mf][nf][h * 2 + 1] = v1;
                rmax[mf][h] = fmaxf(rmax[mf][h], fmaxf(v0, v1));
                int r = wm * 32 + mf * 16 + h * 8 + rq;
                stage[r * 132 + c]     = v0;
                stage[r * 132 + c + 1] = v1;
            }
        }

#pragma unroll
    for (int mf = 0; mf < 2; mf++)
#pragma unroll
        for (int h = 0; h < 2; h++) {
            float m = rmax[mf][h];
            m = fmaxf(m, __shfl_xor_sync(0xffffffff, m, 1));
            m = fmaxf(m, __shfl_xor_sync(0xffffffff, m, 2));
            if (q == 0) redm[wm * 32 + mf * 16 + h * 8 + rq][wn] = m;
        }
    __syncthreads();

#pragma unroll
    for (int mf = 0; mf < 2; mf++)
#pragma unroll
        for (int h = 0; h < 2; h++) {
            int r = wm * 32 + mf * 16 + h * 8 + rq;
            float m = fmaxf(redm[r][0], redm[r][1]);
            float s = 0.f;
#pragma unroll
            for (int nf = 0; nf < 8; nf++) {
                s += __expf(acc[mf][nf][h * 2 + 0] - m);
                s += __expf(acc[mf][nf][h * 2 + 1] - m);
            }
            s += __shfl_xor_sync(0xffffffff, s, 1);
            s += __shfl_xor_sync(0xffffffff, s, 2);
            if (q == 0) reds[r][wn] = s;
        }
    __syncthreads();

    if (tid < 128) {
        float m = fmaxf(redm[tid][0], redm[tid][1]);
        float s = reds[tid][0] + reds[tid][1];
        g_pmax[(size_t)(row0 + tid) * NCB + cb] = m;
        g_psum[(size_t)(row0 + tid) * NCB + cb] = s;
    }

#pragma unroll
    for (int rr = 0; rr < 4; rr++) {
        int r = rr * 32 + warp * 4 + (lane >> 3);
#pragma unroll
        for (int k = 0; k < 4; k++) {
            int col = (lane & 7) * 4 + k * 32;
            float4 v = *(const float4*)&stage[r * 132 + col];
            *(float4*)&out[(size_t)(row0 + r) * NK + col0 + col] = v;
        }
    }
}

// ---------------- kernel 3: merge partials ----------------
__global__ __launch_bounds__(256) void reduce_kernel() {
    int b = blockIdx.x, t = threadIdx.x;
    int wid = t >> 5, lane = t & 31;
    __shared__ float sm[8], ss[8];
    float pm = g_pmax[(size_t)b * NCB + t];
    float ps = g_psum[(size_t)b * NCB + t];
    float M = pm;
#pragma unroll
    for (int o = 16; o; o >>= 1) M = fmaxf(M, __shfl_xor_sync(0xffffffff, M, o));
    if (lane == 0) sm[wid] = M;
    __syncthreads();
    float M0 = sm[lane & 7];
#pragma unroll
    for (int o = 4; o; o >>= 1) M0 = fmaxf(M0, __shfl_xor_sync(0xffffffff, M0, o));
    M = __shfl_sync(0xffffffff, M0, 0);
    float s = ps * __expf(pm - M);
#pragma unroll
    for (int o = 16; o; o >>= 1) s += __shfl_xor_sync(0xffffffff, s, o);
    if (lane == 0) ss[wid] = s;
    __syncthreads();
    if (t == 0) {
        float S = ss[0] + ss[1] + ss[2] + ss[3] + ss[4] + ss[5] + ss[6] + ss[7];
        g_rowm[b] = M;
        g_rowinv[b] = 1.f / S;
    }
}

// ---------------- kernel 4: finalize ----------------
__global__ __launch_bounds__(256) void finalize_kernel(float* __restrict__ out) {
    size_t i = (size_t)blockIdx.x * blockDim.x + threadIdx.x;
    float4* o4 = (float4*)out;
    int b = (int)(i >> 13);
    float m = g_rowm[b], inv = g_rowinv[b];
    float4 v = o4[i];
    v.x = __expf(v.x - m) * inv;
    v.y = __expf(v.y - m) * inv;
    v.z = __expf(v.z - m) * inv;
    v.w = __expf(v.w - m) * inv;
    o4[i] = v;
}

// ---------------- launcher ----------------
extern "C" void kernel_launch(void* const* d_in, const int* in_sizes, int n_in,
                              void* d_out, int out_size) {
    const float* query  = (const float*)d_in[0];
    const float* keys   = (const float*)d_in[1];
    const float* norms  = (const float*)d_in[2];
    const float* sketch = (const float*)d_in[3];
    float* out = (float*)d_out;

    cudaFuncSetAttribute(kd_kernel,   cudaFuncAttributeMaxDynamicSharedMemorySize, SMEM_BYTES);
    cudaFuncSetAttribute(gemm_kernel, cudaFuncAttributeMaxDynamicSharedMemorySize, SMEM_BYTES);

    convert_keys_kernel<<<NK * MM / 1024, 256>>>(keys, norms);
    prep_S_kernel<<<MM * DD / 256, 256>>>(sketch);
    prep_A_kernel<<<BQ * DD / 256, 256>>>(query);
    kd_kernel<<<NK / 128, 256, SMEM_BYTES>>>();
    dim3 ggrid(NCB, BQ / 128);
    gemm_kernel<<<ggrid, 256, SMEM_BYTES>>>(out);
    reduce_kernel<<<BQ, 256>>>();
    finalize_kernel<<<(size_t)BQ * NK / 4 / 256, 256>>>(out);
}

// round 10
// speedup vs baseline: 2.0445x; 1.0101x over previous
#include <cuda_runtime.h>
#include <cuda_bf16.h>
#include <cstdint>

#define BQ   2048
#define DD   128
#define MM   256
#define NK   32768
#define EST_CONST 0.0048957583f   // sqrt(pi/2)/256

#define TILE_N 128
#define NCB    (NK / TILE_N)      // 256 column blocks
#define KMAIN  384                // [Qhi|Qlo|Qhi] x [KDhi|KDhi|KDlo]

// ---------------- device scratch ----------------
__device__ __align__(16) __nv_bfloat16 g_Kb[NK * MM];      // keys bf16 exact
__device__ __align__(16) __nv_bfloat16 g_Sd[DD * 512];     // S^T hi|lo  [d][512]
__device__ __align__(16) __nv_bfloat16 g_Ap[BQ * KMAIN];   // [Qhi|Qlo|Qhi]
__device__ __align__(16) __nv_bfloat16 g_Bp[NK * KMAIN];   // [KDhi|KDhi|KDlo]
__device__ float g_scl[NK];
__device__ float g_pmax[BQ * NCB];
__device__ float g_psum[BQ * NCB];
__device__ float g_rowm[BQ];
__device__ float g_rowinv[BQ];

__device__ __forceinline__ uint32_t smem_u32(const void* p) {
    uint32_t a;
    asm("{ .reg .u64 t; cvta.to.shared.u64 t, %1; cvt.u32.u64 %0, t; }" : "=r"(a) : "l"(p));
    return a;
}
#define CP16(dst, src) asm volatile("cp.async.cg.shared.global [%0], [%1], 16;" :: "r"(dst), "l"(src))
#define CP_COMMIT()    asm volatile("cp.async.commit_group;" ::: "memory")

// ---------------- kernel 0: keys -> bf16 (exact), scales --------------------
__global__ __launch_bounds__(256) void convert_keys_kernel(const float* __restrict__ keys,
                                                           const float* __restrict__ norms) {
    int i = blockIdx.x * blockDim.x + threadIdx.x;   // over float4
    float4 v = ((const float4*)keys)[i];
    __nv_bfloat162* o = (__nv_bfloat162*)g_Kb;
    o[i * 2]     = __nv_bfloat162(__float2bfloat16(v.x), __float2bfloat16(v.y));
    o[i * 2 + 1] = __nv_bfloat162(__float2bfloat16(v.z), __float2bfloat16(v.w));
    if (i < NK) g_scl[i] = EST_CONST * norms[i];
}

// ---------------- kernel 0b: S -> transposed hi/lo --------------------------
__global__ __launch_bounds__(256) void prep_S_kernel(const float* __restrict__ S) {
    int idx = blockIdx.x * blockDim.x + threadIdx.x;   // 32768 elems
    int m = idx >> 7, d = idx & 127;
    float v = S[m * DD + d];
    __nv_bfloat16 hi = __float2bfloat16(v);
    float lo = v - __bfloat162float(hi);
    g_Sd[d * 512 + m]       = hi;
    g_Sd[d * 512 + 256 + m] = __float2bfloat16(lo);
}

// ---------------- kernel 0c: Q -> [Qhi|Qlo|Qhi] -----------------------------
__global__ __launch_bounds__(256) void prep_A_kernel(const float* __restrict__ q) {
    int idx = blockIdx.x * blockDim.x + threadIdx.x;   // 2048*128
    int b = idx >> 7, d = idx & 127;
    float v = q[idx];
    __nv_bfloat16 hi = __float2bfloat16(v);
    float lo = v - __bfloat162float(hi);
    g_Ap[b * KMAIN + d]       = hi;
    g_Ap[b * KMAIN + 128 + d] = __float2bfloat16(lo);
    g_Ap[b * KMAIN + 256 + d] = hi;
}

// ---------------- shared GEMM machinery ----------------
#define RSE 72                          // smem row elems (144 B)
#define TBYTES (128 * RSE * 2)          // 18432 per operand tile
#define STAGE_BYTES (2 * TBYTES)        // 36864
#define SMEM_BYTES  (3 * STAGE_BYTES)   // 110592

extern __shared__ char dsm[];

#define HMMA(acc, a, b0, b1) \
    asm volatile("mma.sync.aligned.m16n8k16.row.col.f32.bf16.bf16.f32 " \
                 "{%0,%1,%2,%3}, {%4,%5,%6,%7}, {%8,%9}, {%0,%1,%2,%3};" \
                 : "+f"((acc)[0]), "+f"((acc)[1]), "+f"((acc)[2]), "+f"((acc)[3]) \
                 : "r"((a)[0]), "r"((a)[1]), "r"((a)[2]), "r"((a)[3]), "r"(b0), "r"(b1))

#define LDSM4(f, addr) \
    asm volatile("ldmatrix.sync.aligned.m8n8.x4.shared.b16 {%0,%1,%2,%3}, [%4];" \
                 : "=r"((f)[0]), "=r"((f)[1]), "=r"((f)[2]), "=r"((f)[3]) : "r"(addr))

// compute one 64-wide K chunk (warp tile 32x64, 4x2 warps)
__device__ __forceinline__ void compute_chunk(uint32_t base, int wm, int wn,
                                              int lrow, int lcolo, float acc[2][8][4]) {
    uint32_t bbase = base + TBYTES;
#pragma unroll
    for (int kk = 0; kk < 64; kk += 16) {
        uint32_t a[2][4];
#pragma unroll
        for (int mf = 0; mf < 2; mf++)
            LDSM4(a[mf], base + (uint32_t)((wm * 32 + mf * 16 + lrow) * (RSE * 2)
                                           + (kk + lcolo) * 2));
        uint32_t b[8][2];
#pragma unroll
        for (int nq = 0; nq < 4; nq++) {
            uint32_t f[4];
            LDSM4(f, bbase + (uint32_t)((wn * 64 + nq * 16 + lrow) * (RSE * 2)
                                        + (kk + lcolo) * 2));
            b[nq * 2][0] = f[0];     b[nq * 2][1] = f[2];
            b[nq * 2 + 1][0] = f[1]; b[nq * 2 + 1][1] = f[3];
        }
#pragma unroll
        for (int mf = 0; mf < 2; mf++)
#pragma unroll
            for (int nf = 0; nf < 8; nf++)
                HMMA(acc[mf][nf], a[mf], b[nf][0], b[nf][1]);
    }
}

__device__ __forceinline__ void load_tiles(uint32_t base, int tid,
                                           const __nv_bfloat16* __restrict__ Ag, int astr,
                                           const __nv_bfloat16* __restrict__ Bg, int bstr) {
#pragma unroll
    for (int i = 0; i < 4; i++) {
        int u = tid + i * 256;
        int r = u >> 3, c = (u & 7) * 8;
        uint32_t off = (uint32_t)(r * (RSE * 2) + c * 2);
        CP16(base + off,          &Ag[(size_t)r * astr + c]);
        CP16(base + TBYTES + off, &Bg[(size_t)r * bstr + c]);
    }
}

// ---------------- kernel 1: KD = keys*S (hi/lo), pack B'  -------------------
// 64-key tiles for parallelism: 512 CTAs; warp tile 16x64 (4x2 warps).
// smem stage: A 64x144B = 9216 | B 128x144B = 18432 -> 27648; x3 = 82944.
#define KD_ABYTES 9216
#define KD_STAGE  27648
#define KD_SMEM   (3 * KD_STAGE)

__device__ __forceinline__ void kd_load(uint32_t base, int tid,
                                        const __nv_bfloat16* __restrict__ Ag,
                                        const __nv_bfloat16* __restrict__ Bg) {
#pragma unroll
    for (int i = 0; i < 2; i++) {         // A: 64 rows x 128B
        int u = tid + i * 256;
        int r = u >> 3, c = (u & 7) * 8;
        CP16(base + (uint32_t)(r * (RSE * 2) + c * 2), &Ag[(size_t)r * MM + c]);
    }
#pragma unroll
    for (int i = 0; i < 4; i++) {         // B: 128 rows x 128B
        int u = tid + i * 256;
        int r = u >> 3, c = (u & 7) * 8;
        CP16(base + KD_ABYTES + (uint32_t)(r * (RSE * 2) + c * 2), &Bg[(size_t)r * 512 + c]);
    }
}

__global__ __launch_bounds__(256, 2) void kd_kernel() {
    uint32_t sb = smem_u32(dsm);
    int tid = threadIdx.x, warp = tid >> 5, lane = tid & 31;
    int wm = warp >> 1, wn = warp & 1;
    int n0 = blockIdx.x * 64;

    float acc[8][4];
#pragma unroll
    for (int j = 0; j < 8; j++)
#pragma unroll
        for (int k = 0; k < 4; k++) acc[j][k] = 0.f;

    int lrow  = (lane & 7) + (lane & 8);
    int lcolo = (lane >> 4) << 3;

#define KD_LOAD(st, c) kd_load(sb + (st) * KD_STAGE, tid, \
        &g_Kb[(size_t)n0 * MM + (((c) * 64) & 255)], &g_Sd[(c) * 64])

    KD_LOAD(0, 0); CP_COMMIT();
    KD_LOAD(1, 1); CP_COMMIT();
#pragma unroll 1
    for (int c = 0; c < 8; c++) {
        if (c < 7) asm volatile("cp.async.wait_group 1;" ::: "memory");
        else       asm volatile("cp.async.wait_group 0;" ::: "memory");
        __syncthreads();
        if (c + 2 < 8) { KD_LOAD((c + 2) % 3, c + 2); CP_COMMIT(); }
        uint32_t base = sb + (c % 3) * KD_STAGE;
        uint32_t bbase = base + KD_ABYTES;
#pragma unroll
        for (int kk = 0; kk < 64; kk += 16) {
            uint32_t a[4];
            LDSM4(a, base + (uint32_t)((wm * 16 + lrow) * (RSE * 2) + (kk + lcolo) * 2));
            uint32_t b[8][2];
#pragma unroll
            for (int nq = 0; nq < 4; nq++) {
                uint32_t f[4];
                LDSM4(f, bbase + (uint32_t)((wn * 64 + nq * 16 + lrow) * (RSE * 2)
                                            + (kk + lcolo) * 2));
                b[nq * 2][0] = f[0];     b[nq * 2][1] = f[2];
                b[nq * 2 + 1][0] = f[1]; b[nq * 2 + 1][1] = f[3];
            }
#pragma unroll
            for (int nf = 0; nf < 8; nf++)
                HMMA(acc[nf], a, b[nf][0], b[nf][1]);
        }
    }

    // epilogue: hi/lo split, pack [KDhi|KDhi|KDlo]
    int q = lane & 3, rq = lane >> 2;
#pragma unroll
    for (int nf = 0; nf < 8; nf++) {
        int col = wn * 64 + nf * 8 + q * 2;
#pragma unroll
        for (int h = 0; h < 2; h++) {
            int r = wm * 16 + h * 8 + rq;
            float v0 = acc[nf][h * 2 + 0];
            float v1 = acc[nf][h * 2 + 1];
            __nv_bfloat16 h0 = __float2bfloat16(v0);
            __nv_bfloat16 h1 = __float2bfloat16(v1);
            __nv_bfloat162 hp(h0, h1);
            __nv_bfloat162 lp(__float2bfloat16(v0 - __bfloat162float(h0)),
                              __float2bfloat16(v1 - __bfloat162float(h1)));
            size_t rb = (size_t)(n0 + r) * KMAIN;
            *(__nv_bfloat162*)&g_Bp[rb + col]       = hp;
            *(__nv_bfloat162*)&g_Bp[rb + 128 + col] = hp;
            *(__nv_bfloat162*)&g_Bp[rb + 256 + col] = lp;
        }
    }
}

// ---------------- kernel 2: main GEMM 2048x32768, K=384 + partials ----------
__global__ __launch_bounds__(256, 2) void gemm_kernel(float* __restrict__ out) {
    uint32_t sb = smem_u32(dsm);
    int tid = threadIdx.x, warp = tid >> 5, lane = tid & 31;
    int wm = warp >> 1, wn = warp & 1;
    int rb = blockIdx.y, cb = blockIdx.x;
    int row0 = rb * 128, col0 = cb * TILE_N;

    __shared__ float sclS[TILE_N];
    __shared__ float redm[128][2];
    __shared__ float reds[128][2];
    if (tid < TILE_N) sclS[tid] = g_scl[col0 + tid];

    float acc[2][8][4];
#pragma unroll
    for (int i = 0; i < 2; i++)
#pragma unroll
        for (int j = 0; j < 8; j++)
#pragma unroll
            for (int k = 0; k < 4; k++) acc[i][j][k] = 0.f;

    int lrow  = (lane & 7) + (lane & 8);
    int lcolo = (lane >> 4) << 3;

#define MG_LOAD(st, c) load_tiles(sb + (st) * STAGE_BYTES, tid, \
        &g_Ap[(size_t)row0 * KMAIN + (c) * 64], KMAIN, \
        &g_Bp[(size_t)col0 * KMAIN + (c) * 64], KMAIN)

    MG_LOAD(0, 0); CP_COMMIT();
    MG_LOAD(1, 1); CP_COMMIT();
#pragma unroll 1
    for (int c = 0; c < 6; c++) {
        if (c < 5) asm volatile("cp.async.wait_group 1;" ::: "memory");
        else       asm volatile("cp.async.wait_group 0;" ::: "memory");
        __syncthreads();
        if (c + 2 < 6) { MG_LOAD((c + 2) % 3, c + 2); CP_COMMIT(); }
        compute_chunk(sb + (c % 3) * STAGE_BYTES, wm, wn, lrow, lcolo, acc);
    }
    __syncthreads();     // all compute done before epilogue aliases buffers

    // ---------------- epilogue ----------------
    float* stage = (float*)dsm;            // [128][132] fp32
    int q = lane & 3, rq = lane >> 2;

    float rmax[2][2];
#pragma unroll
    for (int mf = 0; mf < 2; mf++)
#pragma unroll
        for (int h = 0; h < 2; h++) rmax[mf][h] = -1e30f;

#pragma unroll
    for (int mf = 0; mf < 2; mf++)
#pragma unroll
        for (int nf = 0; nf < 8; nf++) {
            int c = wn * 64 + nf * 8 + q * 2;
            float s0 = sclS[c], s1 = sclS[c + 1];
#pragma unroll
            for (int h = 0; h < 2; h++) {
                float v0 = acc[mf][nf][h * 2 + 0] * s0;
                float v1 = acc[mf][nf][h * 2 + 1] * s1;
                acc[mf][nf][h * 2 + 0] = v0;
                acc[mf][nf][h * 2 + 1] = v1;
                rmax[mf][h] = fmaxf(rmax[mf][h], fmaxf(v0, v1));
                int r = wm * 32 + mf * 16 + h * 8 + rq;
                stage[r * 132 + c]     = v0;
                stage[r * 132 + c + 1] = v1;
            }
        }

#pragma unroll
    for (int mf = 0; mf < 2; mf++)
#pragma unroll
        for (int h = 0; h < 2; h++) {
            float m = rmax[mf][h];
            m = fmaxf(m, __shfl_xor_sync(0xffffffff, m, 1));
            m = fmaxf(m, __shfl_xor_sync(0xffffffff, m, 2));
            if (q == 0) redm[wm * 32 + mf * 16 + h * 8 + rq][wn] = m;
        }
    __syncthreads();

#pragma unroll
    for (int mf = 0; mf < 2; mf++)
#pragma unroll
        for (int h = 0; h < 2; h++) {
            int r = wm * 32 + mf * 16 + h * 8 + rq;
            float m = fmaxf(redm[r][0], redm[r][1]);
            float s = 0.f;
#pragma unroll
            for (int nf = 0; nf < 8; nf++) {
                s += __expf(acc[mf][nf][h * 2 + 0] - m);
                s += __expf(acc[mf][nf][h * 2 + 1] - m);
            }
            s += __shfl_xor_sync(0xffffffff, s, 1);
            s += __shfl_xor_sync(0xffffffff, s, 2);
            if (q == 0) reds[r][wn] = s;
        }
    __syncthreads();

    if (tid < 128) {
        float m = fmaxf(redm[tid][0], redm[tid][1]);
        float s = reds[tid][0] + reds[tid][1];
        g_pmax[(size_t)(row0 + tid) * NCB + cb] = m;
        g_psum[(size_t)(row0 + tid) * NCB + cb] = s;
    }

#pragma unroll
    for (int rr = 0; rr < 4; rr++) {
        int r = rr * 32 + warp * 4 + (lane >> 3);
#pragma unroll
        for (int k = 0; k < 4; k++) {
            int col = (lane & 7) * 4 + k * 32;
            float4 v = *(const float4*)&stage[r * 132 + col];
            *(float4*)&out[(size_t)(row0 + r) * NK + col0 + col] = v;
        }
    }
}

// ---------------- kernel 3: merge partials (4 rows per block, float4) -------
__global__ __launch_bounds__(256) void reduce_kernel() {
    int t = threadIdx.x;
    int sub = t >> 6, l = t & 63;
    int lane = t & 31, w = (t >> 5) & 1;
    int b = blockIdx.x * 4 + sub;
    __shared__ float sm[4][2], ss[4][2];
    float4 pm = ((const float4*)&g_pmax[(size_t)b * NCB])[l];
    float4 ps = ((const float4*)&g_psum[(size_t)b * NCB])[l];
    float M = fmaxf(fmaxf(pm.x, pm.y), fmaxf(pm.z, pm.w));
#pragma unroll
    for (int o = 16; o; o >>= 1) M = fmaxf(M, __shfl_xor_sync(0xffffffff, M, o));
    if (lane == 0) sm[sub][w] = M;
    __syncthreads();
    M = fmaxf(sm[sub][0], sm[sub][1]);
    float s = ps.x * __expf(pm.x - M) + ps.y * __expf(pm.y - M)
            + ps.z * __expf(pm.z - M) + ps.w * __expf(pm.w - M);
#pragma unroll
    for (int o = 16; o; o >>= 1) s += __shfl_xor_sync(0xffffffff, s, o);
    if (lane == 0) ss[sub][w] = s;
    __syncthreads();
    if (l == 0) {
        g_rowm[b] = M;
        g_rowinv[b] = 1.f / (ss[sub][0] + ss[sub][1]);
    }
}

// ---------------- kernel 4: finalize, 4x ILP per thread ----------------------
__global__ __launch_bounds__(256) void finalize_kernel(float* __restrict__ out) {
    size_t seg = (size_t)blockIdx.x * 1024;       // float4 units; 8 blocks per row
    int b = (int)(blockIdx.x >> 3);
    float m = g_rowm[b], inv = g_rowinv[b];
    float4* o4 = (float4*)out;
    float4 v[4];
#pragma unroll
    for (int k = 0; k < 4; k++) v[k] = o4[seg + threadIdx.x + k * 256];
#pragma unroll
    for (int k = 0; k < 4; k++) {
        v[k].x = __expf(v[k].x - m) * inv;
        v[k].y = __expf(v[k].y - m) * inv;
        v[k].z = __expf(v[k].z - m) * inv;
        v[k].w = __expf(v[k].w - m) * inv;
    }
#pragma unroll
    for (int k = 0; k < 4; k++) o4[seg + threadIdx.x + k * 256] = v[k];
}

// ---------------- launcher ----------------
extern "C" void kernel_launch(void* const* d_in, const int* in_sizes, int n_in,
                              void* d_out, int out_size) {
    const float* query  = (const float*)d_in[0];
    const float* keys   = (const float*)d_in[1];
    const float* norms  = (const float*)d_in[2];
    const float* sketch = (const float*)d_in[3];
    float* out = (float*)d_out;

    cudaFuncSetAttribute(kd_kernel,   cudaFuncAttributeMaxDynamicSharedMemorySize, KD_SMEM);
    cudaFuncSetAttribute(gemm_kernel, cudaFuncAttributeMaxDynamicSharedMemorySize, SMEM_BYTES);

    convert_keys_kernel<<<NK * MM / 1024, 256>>>(keys, norms);
    prep_S_kernel<<<MM * DD / 256, 256>>>(sketch);
    prep_A_kernel<<<BQ * DD / 256, 256>>>(query);
    kd_kernel<<<NK / 64, 256, KD_SMEM>>>();
    dim3 ggrid(NCB, BQ / 128);
    gemm_kernel<<<ggrid, 256, SMEM_BYTES>>>(out);
    reduce_kernel<<<BQ / 4, 256>>>();
    finalize_kernel<<<BQ * 8, 256>>>(out);
}